// round 1
// baseline (speedup 1.0000x reference)
#include <cuda_runtime.h>

// y = x * 2 + 3, elementwise over 67,108,864 fp32 elements.
// float4 vectorized, exact-cover grid (no tail: 64*2048*512 % 4 == 0).

__global__ __launch_bounds__(256) void fma_stream_kernel(
    const float4* __restrict__ in, float4* __restrict__ out)
{
    const unsigned idx = blockIdx.x * blockDim.x + threadIdx.x;
    float4 v = in[idx];
    v.x = fmaf(v.x, 2.0f, 3.0f);
    v.y = fmaf(v.y, 2.0f, 3.0f);
    v.z = fmaf(v.z, 2.0f, 3.0f);
    v.w = fmaf(v.w, 2.0f, 3.0f);
    out[idx] = v;
}

extern "C" void kernel_launch(void* const* d_in, const int* in_sizes, int n_in,
                              void* d_out, int out_size) {
    const float4* in = (const float4*)d_in[0];
    float4* out = (float4*)d_out;
    const long long n = (long long)in_sizes[0];       // 67,108,864
    const long long nvec = n / 4;                     // 16,777,216
    const int threads = 256;
    const int blocks = (int)((nvec + threads - 1) / threads);  // 65,536
    fma_stream_kernel<<<blocks, threads>>>(in, out);
}

// round 2
// speedup vs baseline: 1.0133x; 1.0133x over previous
#include <cuda_runtime.h>

// y = x * 2 + 3 over 67,108,864 fp32 (read-once/write-once stream).
// float4 x4 per thread, grid-strided offsets (fully coalesced), front-batched
// loads for MLP=4, evict-streaming cache hints (__ldcs/__stcs).
//
// nvec = 16,777,216 float4; 16,384 blocks x 256 threads x 4 float4 = exact cover.

__global__ __launch_bounds__(256) void fma_stream4_kernel(
    const float4* __restrict__ in, float4* __restrict__ out)
{
    const unsigned tid    = blockIdx.x * blockDim.x + threadIdx.x;
    const unsigned stride = gridDim.x * blockDim.x;   // 4,194,304

    // Front-batch all 4 loads -> 4 outstanding LDG.128 per thread.
    float4 v0 = __ldcs(in + tid);
    float4 v1 = __ldcs(in + tid + stride);
    float4 v2 = __ldcs(in + tid + 2u * stride);
    float4 v3 = __ldcs(in + tid + 3u * stride);

    v0.x = fmaf(v0.x, 2.0f, 3.0f); v0.y = fmaf(v0.y, 2.0f, 3.0f);
    v0.z = fmaf(v0.z, 2.0f, 3.0f); v0.w = fmaf(v0.w, 2.0f, 3.0f);
    v1.x = fmaf(v1.x, 2.0f, 3.0f); v1.y = fmaf(v1.y, 2.0f, 3.0f);
    v1.z = fmaf(v1.z, 2.0f, 3.0f); v1.w = fmaf(v1.w, 2.0f, 3.0f);
    v2.x = fmaf(v2.x, 2.0f, 3.0f); v2.y = fmaf(v2.y, 2.0f, 3.0f);
    v2.z = fmaf(v2.z, 2.0f, 3.0f); v2.w = fmaf(v2.w, 2.0f, 3.0f);
    v3.x = fmaf(v3.x, 2.0f, 3.0f); v3.y = fmaf(v3.y, 2.0f, 3.0f);
    v3.z = fmaf(v3.z, 2.0f, 3.0f); v3.w = fmaf(v3.w, 2.0f, 3.0f);

    __stcs(out + tid,               v0);
    __stcs(out + tid + stride,      v1);
    __stcs(out + tid + 2u * stride, v2);
    __stcs(out + tid + 3u * stride, v3);
}

extern "C" void kernel_launch(void* const* d_in, const int* in_sizes, int n_in,
                              void* d_out, int out_size) {
    const float4* in = (const float4*)d_in[0];
    float4* out = (float4*)d_out;
    const long long n    = (long long)in_sizes[0];   // 67,108,864
    const long long nvec = n / 4;                    // 16,777,216
    const int threads = 256;
    const int vec_per_thread = 4;
    const int blocks = (int)(nvec / ((long long)threads * vec_per_thread)); // 16,384
    fma_stream4_kernel<<<blocks, threads>>>(in, out);
}